// round 15
// baseline (speedup 1.0000x reference)
#include <cuda_runtime.h>
#include <math.h>
#include <cstdint>

// ---------------------------------------------------------------------------
// Round 15: dual row-tile (M=32/warp) at 12 warps/SM. TPB=384, 1 CTA/SM,
// 170 regs: feat hoist dropped, phase B in N-halves, phases C/E in N-quarters.
// fp16 m16n8k16, MUFU tanh, resident 85KB fragment blob, barrier-free loop,
// per-warp tail guard (BLK_ROWS=384 does not divide B).
// Output: [action B*6 | vf B*128 | expout B*12] fp32.
// ---------------------------------------------------------------------------

static constexpr int TPB = 384;
static constexpr int BLK_ROWS = 384;   // 12 warps x 32 rows

// blob offsets in uint4 units: [(kc*NTP+ntp)*32+lane] -> {b0e,b1e,b0o,b1o}
static constexpr int WS0_4 = 0;        // KC=8, NTP=8  -> 2048
static constexpr int WS1_4 = 2048;     // KC=8, NTP=4  -> 1024
static constexpr int WV_4  = 3072;     // KC=4, NTP=8  -> 1024
static constexpr int WE1_4 = 4096;     // KC=4, NTP=8  -> 1024
static constexpr int W2_4  = 5120;     // KC=8, NTP=1  -> 256
static constexpr int G_4   = 5376;     // KC=4 as uint2[128] -> 64 u4
static constexpr int PACK_U4 = 5440;
static constexpr int SMEM_BYTES = PACK_U4 * 16;   // 87040

__device__ __align__(16) uint4 g_pack[PACK_U4];

__device__ __forceinline__ unsigned pack_h2(float lo, float hi) {
    unsigned p;
    asm("cvt.rn.f16x2.f32 %0, %1, %2;" : "=r"(p) : "f"(hi), "f"(lo));
    return p;
}
__device__ __forceinline__ float tanh_mufu(float x) {
    float y;
    asm("tanh.approx.f32 %0, %1;" : "=f"(y) : "f"(x));
    return y;
}
__device__ __forceinline__ float softplus_fast(float x) {
    return fmaxf(x, 0.f) + log1pf(__expf(-fabsf(x)));
}

// ============================ prologue (same as R13/R14) =====================
__global__ void pack_weights(const float* __restrict__ Ws0,
                             const float* __restrict__ Ws1,
                             const float* __restrict__ Wv,
                             const float* __restrict__ We1,
                             const float* __restrict__ wg,
                             const float* __restrict__ wn,
                             const float* __restrict__ We2) {
    int idx = blockIdx.x * blockDim.x + threadIdx.x;
    if (idx >= 5504) return;
    int lane, r, c;

    if (idx < 5376) {
        int base, NTP, panel;
        int i = idx;
        if (i < 2048)      { base = WS0_4; NTP = 8; panel = 0; }
        else if (i < 3072) { base = WS1_4; NTP = 4; panel = 1; i -= 2048; }
        else if (i < 4096) { base = WV_4;  NTP = 8; panel = 2; i -= 3072; }
        else if (i < 5120) { base = WE1_4; NTP = 8; panel = 3; i -= 4096; }
        else               { base = W2_4;  NTP = 1; panel = 4; i -= 5120; }
        lane = i & 31; r = lane >> 2; c = lane & 3;
        int t = i >> 5, ntp = t % NTP, kc = t / NTP;
        int k0 = kc * 16 + 2 * c;

        auto W = [&](int k, int n) -> float {
            switch (panel) {
                case 0: return Ws0[k * 128 + n];
                case 1: return (n < 62) ? Ws1[k * 62 + n] : 0.f;
                case 2: return (k < 62) ? Wv[k * 128 + n] : 0.f;
                case 3: {
                    int e = n >> 6, hid = n & 63;
                    return (k < 62) ? We1[((e * 62 + k) << 6) + hid] : 0.f;
                }
                default: {
                    if (n >= 12) return 0.f;
                    int e = n / 6, o = n - e * 6;
                    return ((k >> 6) == e) ? We2[e * 384 + (k & 63) * 6 + o] : 0.f;
                }
            }
        };
        uint4 q;
        int ne = (2 * ntp) * 8 + r, no = ne + 8;
        q.x = pack_h2(W(k0, ne), W(k0 + 1, ne));
        q.y = pack_h2(W(k0 + 8, ne), W(k0 + 9, ne));
        q.z = pack_h2(W(k0, no), W(k0 + 1, no));
        q.w = pack_h2(W(k0 + 8, no), W(k0 + 9, no));
        g_pack[base + (kc * NTP + ntp) * 32 + lane] = q;
    } else {
        int i = idx - 5376;
        lane = i & 31; r = lane >> 2; c = lane & 3;
        int kc = i >> 5;
        int k0 = kc * 16 + 2 * c, n = r;
        auto G = [&](int k) -> float {
            if (k >= 62) return 0.f;
            if (n < 2) return wg[k * 2 + n];
            if (n < 4) return wn[k * 2 + (n - 2)];
            return 0.f;
        };
        uint2* g2 = (uint2*)(g_pack + G_4);
        g2[kc * 32 + lane] = make_uint2(pack_h2(G(k0), G(k0 + 1)),
                                        pack_h2(G(k0 + 8), G(k0 + 9)));
    }
}

// ============================ MMA helpers ====================================
__device__ __forceinline__ void mma16(float d[4], unsigned a0, unsigned a1,
                                      unsigned a2, unsigned a3,
                                      unsigned b0, unsigned b1) {
    asm("mma.sync.aligned.m16n8k16.row.col.f32.f16.f16.f32 "
        "{%0,%1,%2,%3},{%4,%5,%6,%7},{%8,%9},{%0,%1,%2,%3};"
        : "+f"(d[0]), "+f"(d[1]), "+f"(d[2]), "+f"(d[3])
        : "r"(a0), "r"(a1), "r"(a2), "r"(a3), "r"(b0), "r"(b1));
}

// dual-tile panel: one B-fragment load feeds both row tiles
template <int KC, int NTPh, int NTPtot, int UNR>
__device__ __forceinline__ void mma_dual(const uint4* __restrict__ P, int ntp0,
                                         const unsigned (&a0)[KC][4],
                                         const unsigned (&a1)[KC][4],
                                         float (&c0)[2 * NTPh][4],
                                         float (&c1)[2 * NTPh][4], int lane) {
#pragma unroll UNR
    for (int kc = 0; kc < KC; kc++) {
        const uint4* pk = P + (kc * NTPtot + ntp0) * 32 + lane;
#pragma unroll
        for (int ntp = 0; ntp < NTPh; ntp++) {
            uint4 q = pk[ntp * 32];
            mma16(c0[2 * ntp],     a0[kc][0], a0[kc][1], a0[kc][2], a0[kc][3], q.x, q.y);
            mma16(c0[2 * ntp + 1], a0[kc][0], a0[kc][1], a0[kc][2], a0[kc][3], q.z, q.w);
            mma16(c1[2 * ntp],     a1[kc][0], a1[kc][1], a1[kc][2], a1[kc][3], q.x, q.y);
            mma16(c1[2 * ntp + 1], a1[kc][0], a1[kc][1], a1[kc][2], a1[kc][3], q.z, q.w);
        }
    }
}

template <int NT> __device__ __forceinline__ void zacc(float (&acc)[NT][4]) {
#pragma unroll
    for (int i = 0; i < NT; i++)
#pragma unroll
        for (int j = 0; j < 4; j++) acc[i][j] = 0.f;
}

__device__ __forceinline__ float qmax(float v) {
    v = fmaxf(v, __shfl_xor_sync(0xffffffffu, v, 1));
    v = fmaxf(v, __shfl_xor_sync(0xffffffffu, v, 2));
    return v;
}
__device__ __forceinline__ float qsum(float v) {
    v += __shfl_xor_sync(0xffffffffu, v, 1);
    v += __shfl_xor_sync(0xffffffffu, v, 2);
    return v;
}

// ============================ main kernel ====================================
__global__ void __launch_bounds__(TPB, 1) mlp_fused_kernel(
    const float* __restrict__ feat,   const float* __restrict__ noise,
    const float* __restrict__ bs0,    const float* __restrict__ bs1,
    const float* __restrict__ bv,     const float* __restrict__ be1,
    const float* __restrict__ be2,
    float* __restrict__ out_action, float* __restrict__ out_vf,
    float* __restrict__ out_expout, int nblk, int Btot)
{
    extern __shared__ uint4 sPk[];

    const int tid  = threadIdx.x;
    const int lane = tid & 31;
    const int wrow = (tid >> 5) * 32;
    const int r = lane >> 2, c = lane & 3;
    const int base = lane & ~3;

    for (int i = tid; i < PACK_U4; i += TPB) sPk[i] = g_pack[i];
    __syncthreads();
    const uint2* sG2 = (const uint2*)(sPk + G_4);

    for (int blk = blockIdx.x; blk < nblk; blk += gridDim.x) {
        const int rowbase = blk * BLK_ROWS;
        if (rowbase + wrow + 32 > Btot) continue;   // whole-warp tail guard
        const int row0 = rowbase + wrow + r;        // tile0 first row
        // tile0 rows: row0, row0+8 ; tile1 rows: row0+16, row0+24

        // =============== Phase A: h = tanh(feat @ Ws0 + bs0) — N-halves ====
        unsigned aH0[8][4], aH1[8][4];
        {
            const float* f0 = feat + (size_t)row0 * 128;
#pragma unroll
            for (int h = 0; h < 2; h++) {
                float a0[8][4], a1[8][4];
                zacc(a0); zacc(a1);
#pragma unroll 4
                for (int kc = 0; kc < 8; kc++) {
                    int k0 = kc * 16 + 2 * c;
                    float2 x0 = *(const float2*)(f0 + k0);
                    float2 x1 = *(const float2*)(f0 + 8 * 128 + k0);
                    float2 x2 = *(const float2*)(f0 + k0 + 8);
                    float2 x3 = *(const float2*)(f0 + 8 * 128 + k0 + 8);
                    unsigned u0 = pack_h2(x0.x, x0.y);
                    unsigned u1 = pack_h2(x1.x, x1.y);
                    unsigned u2 = pack_h2(x2.x, x2.y);
                    unsigned u3 = pack_h2(x3.x, x3.y);
                    float2 y0 = *(const float2*)(f0 + 16 * 128 + k0);
                    float2 y1 = *(const float2*)(f0 + 24 * 128 + k0);
                    float2 y2 = *(const float2*)(f0 + 16 * 128 + k0 + 8);
                    float2 y3 = *(const float2*)(f0 + 24 * 128 + k0 + 8);
                    unsigned v0 = pack_h2(y0.x, y0.y);
                    unsigned v1 = pack_h2(y1.x, y1.y);
                    unsigned v2 = pack_h2(y2.x, y2.y);
                    unsigned v3 = pack_h2(y3.x, y3.y);
                    const uint4* pk = sPk + WS0_4 + (kc * 8 + 4 * h) * 32 + lane;
#pragma unroll
                    for (int ntp = 0; ntp < 4; ntp++) {
                        uint4 q = pk[ntp * 32];
                        mma16(a0[2 * ntp],     u0, u1, u2, u3, q.x, q.y);
                        mma16(a0[2 * ntp + 1], u0, u1, u2, u3, q.z, q.w);
                        mma16(a1[2 * ntp],     v0, v1, v2, v3, q.x, q.y);
                        mma16(a1[2 * ntp + 1], v0, v1, v2, v3, q.z, q.w);
                    }
                }
#pragma unroll
                for (int p = 0; p < 4; p++) {
                    int kp = 4 * h + p;
                    float2 b0 = *(const float2*)&bs0[(2 * kp) * 8 + 2 * c];
                    float2 b1 = *(const float2*)&bs0[(2 * kp + 1) * 8 + 2 * c];
                    aH0[kp][0] = pack_h2(tanh_mufu(a0[2 * p][0] + b0.x),
                                         tanh_mufu(a0[2 * p][1] + b0.y));
                    aH0[kp][1] = pack_h2(tanh_mufu(a0[2 * p][2] + b0.x),
                                         tanh_mufu(a0[2 * p][3] + b0.y));
                    aH0[kp][2] = pack_h2(tanh_mufu(a0[2 * p + 1][0] + b1.x),
                                         tanh_mufu(a0[2 * p + 1][1] + b1.y));
                    aH0[kp][3] = pack_h2(tanh_mufu(a0[2 * p + 1][2] + b1.x),
                                         tanh_mufu(a0[2 * p + 1][3] + b1.y));
                    aH1[kp][0] = pack_h2(tanh_mufu(a1[2 * p][0] + b0.x),
                                         tanh_mufu(a1[2 * p][1] + b0.y));
                    aH1[kp][1] = pack_h2(tanh_mufu(a1[2 * p][2] + b0.x),
                                         tanh_mufu(a1[2 * p][3] + b0.y));
                    aH1[kp][2] = pack_h2(tanh_mufu(a1[2 * p + 1][0] + b1.x),
                                         tanh_mufu(a1[2 * p + 1][1] + b1.y));
                    aH1[kp][3] = pack_h2(tanh_mufu(a1[2 * p + 1][2] + b1.x),
                                         tanh_mufu(a1[2 * p + 1][3] + b1.y));
                }
            }
        }

        // =============== Phase B: la = tanh(h @ Ws1 + bs1) — N-halves ======
        unsigned laA0[4][4], laA1[4][4];
#pragma unroll
        for (int h = 0; h < 2; h++) {
            float a0[4][4], a1[4][4];
            zacc(a0); zacc(a1);
            mma_dual<8, 2, 4, 4>(sPk + WS1_4, 2 * h, aH0, aH1, a0, a1, lane);
#pragma unroll
            for (int p = 0; p < 2; p++) {
                int kp = 2 * h + p;
                int c0 = (2 * kp) * 8 + 2 * c, c1 = (2 * kp + 1) * 8 + 2 * c;
                float b0x = (c0 < 62) ? bs1[c0] : 0.f;
                float b0y = (c0 + 1 < 62) ? bs1[c0 + 1] : 0.f;
                float b1x = (c1 < 62) ? bs1[c1] : 0.f;
                float b1y = (c1 + 1 < 62) ? bs1[c1 + 1] : 0.f;
                laA0[kp][0] = pack_h2(tanh_mufu(a0[2 * p][0] + b0x),
                                      tanh_mufu(a0[2 * p][1] + b0y));
                laA0[kp][1] = pack_h2(tanh_mufu(a0[2 * p][2] + b0x),
                                      tanh_mufu(a0[2 * p][3] + b0y));
                laA0[kp][2] = pack_h2(tanh_mufu(a0[2 * p + 1][0] + b1x),
                                      tanh_mufu(a0[2 * p + 1][1] + b1y));
                laA0[kp][3] = pack_h2(tanh_mufu(a0[2 * p + 1][2] + b1x),
                                      tanh_mufu(a0[2 * p + 1][3] + b1y));
                laA1[kp][0] = pack_h2(tanh_mufu(a1[2 * p][0] + b0x),
                                      tanh_mufu(a1[2 * p][1] + b0y));
                laA1[kp][1] = pack_h2(tanh_mufu(a1[2 * p][2] + b0x),
                                      tanh_mufu(a1[2 * p][3] + b0y));
                laA1[kp][2] = pack_h2(tanh_mufu(a1[2 * p + 1][0] + b1x),
                                      tanh_mufu(a1[2 * p + 1][1] + b1y));
                laA1[kp][3] = pack_h2(tanh_mufu(a1[2 * p + 1][2] + b1x),
                                      tanh_mufu(a1[2 * p + 1][3] + b1y));
            }
        }

        // =============== Gating, both tiles (warp-local) ===================
        float gate[2][4];   // [tile][gA0,gA1,gB0,gB1]
#pragma unroll
        for (int t = 0; t < 2; t++) {
            float g[4] = {0.f, 0.f, 0.f, 0.f};
#pragma unroll
            for (int kc = 0; kc < 4; kc++) {
                uint2 b = sG2[kc * 32 + lane];
                if (t == 0)
                    mma16(g, laA0[kc][0], laA0[kc][1], laA0[kc][2], laA0[kc][3], b.x, b.y);
                else
                    mma16(g, laA1[kc][0], laA1[kc][1], laA1[kc][2], laA1[kc][3], b.x, b.y);
            }
            float cl0  = __shfl_sync(0xffffffffu, g[0], base);
            float cl1  = __shfl_sync(0xffffffffu, g[1], base);
            float cl0b = __shfl_sync(0xffffffffu, g[2], base);
            float cl1b = __shfl_sync(0xffffffffu, g[3], base);
            float n0p  = __shfl_sync(0xffffffffu, g[0], base + 1);
            float n1p  = __shfl_sync(0xffffffffu, g[1], base + 1);
            float n0pb = __shfl_sync(0xffffffffu, g[2], base + 1);
            float n1pb = __shfl_sync(0xffffffffu, g[3], base + 1);
            int rA = row0 + 16 * t, rB = rA + 8;
            float2 nzA = *(const float2*)&noise[(size_t)rA * 2];
            float2 nzB = *(const float2*)&noise[(size_t)rB * 2];
            {
                float z0 = fmaf(nzA.x, softplus_fast(n0p) + 1e-2f, cl0);
                float z1 = fmaf(nzA.y, softplus_fast(n1p) + 1e-2f, cl1);
                float mx = fmaxf(z0, z1);
                float e0 = __expf(z0 - mx), e1 = __expf(z1 - mx);
                float inv = 1.f / (e0 + e1);
                gate[t][0] = e0 * inv; gate[t][1] = e1 * inv;
            }
            {
                float z0 = fmaf(nzB.x, softplus_fast(n0pb) + 1e-2f, cl0b);
                float z1 = fmaf(nzB.y, softplus_fast(n1pb) + 1e-2f, cl1b);
                float mx = fmaxf(z0, z1);
                float e0 = __expf(z0 - mx), e1 = __expf(z1 - mx);
                float inv = 1.f / (e0 + e1);
                gate[t][2] = e0 * inv; gate[t][3] = e1 * inv;
            }
        }

        // =============== Phase C: vf = tanh(la @ Wv + bv) — N-quarters =====
#pragma unroll
        for (int h = 0; h < 4; h++) {
            float a0[4][4], a1[4][4];
            zacc(a0); zacc(a1);
            mma_dual<4, 2, 8, 4>(sPk + WV_4, 2 * h, laA0, laA1, a0, a1, lane);
#pragma unroll
            for (int nt = 0; nt < 4; nt++) {
                int col = 32 * h + nt * 8 + 2 * c;
                float2 bb = *(const float2*)&bv[col];
                float2 o00, o01, o10, o11;
                o00.x = tanh_mufu(a0[nt][0] + bb.x);
                o00.y = tanh_mufu(a0[nt][1] + bb.y);
                o01.x = tanh_mufu(a0[nt][2] + bb.x);
                o01.y = tanh_mufu(a0[nt][3] + bb.y);
                o10.x = tanh_mufu(a1[nt][0] + bb.x);
                o10.y = tanh_mufu(a1[nt][1] + bb.y);
                o11.x = tanh_mufu(a1[nt][2] + bb.x);
                o11.y = tanh_mufu(a1[nt][3] + bb.y);
                __stcs((float2*)&out_vf[(size_t)(row0) * 128 + col],      o00);
                __stcs((float2*)&out_vf[(size_t)(row0 + 8) * 128 + col],  o01);
                __stcs((float2*)&out_vf[(size_t)(row0 + 16) * 128 + col], o10);
                __stcs((float2*)&out_vf[(size_t)(row0 + 24) * 128 + col], o11);
            }
        }

        // =============== Phase E: eh = relu(la @ We1 + be1) — N-quarters ===
        unsigned ehA0[8][4], ehA1[8][4];
#pragma unroll
        for (int h = 0; h < 4; h++) {
            float a0[4][4], a1[4][4];
            zacc(a0); zacc(a1);
            mma_dual<4, 2, 8, 4>(sPk + WE1_4, 2 * h, laA0, laA1, a0, a1, lane);
#pragma unroll
            for (int p = 0; p < 2; p++) {
                int kp = 2 * h + p;
                float2 b0 = *(const float2*)&be1[(2 * kp) * 8 + 2 * c];
                float2 b1 = *(const float2*)&be1[(2 * kp + 1) * 8 + 2 * c];
                ehA0[kp][0] = pack_h2(fmaxf(a0[2 * p][0] + b0.x, 0.f),
                                      fmaxf(a0[2 * p][1] + b0.y, 0.f));
                ehA0[kp][1] = pack_h2(fmaxf(a0[2 * p][2] + b0.x, 0.f),
                                      fmaxf(a0[2 * p][3] + b0.y, 0.f));
                ehA0[kp][2] = pack_h2(fmaxf(a0[2 * p + 1][0] + b1.x, 0.f),
                                      fmaxf(a0[2 * p + 1][1] + b1.y, 0.f));
                ehA0[kp][3] = pack_h2(fmaxf(a0[2 * p + 1][2] + b1.x, 0.f),
                                      fmaxf(a0[2 * p + 1][3] + b1.y, 0.f));
                ehA1[kp][0] = pack_h2(fmaxf(a1[2 * p][0] + b0.x, 0.f),
                                      fmaxf(a1[2 * p][1] + b0.y, 0.f));
                ehA1[kp][1] = pack_h2(fmaxf(a1[2 * p][2] + b0.x, 0.f),
                                      fmaxf(a1[2 * p][3] + b0.y, 0.f));
                ehA1[kp][2] = pack_h2(fmaxf(a1[2 * p + 1][0] + b1.x, 0.f),
                                      fmaxf(a1[2 * p + 1][1] + b1.y, 0.f));
                ehA1[kp][3] = pack_h2(fmaxf(a1[2 * p + 1][2] + b1.x, 0.f),
                                      fmaxf(a1[2 * p + 1][3] + b1.y, 0.f));
            }
        }

        // =============== Phase F1: logits (N=16) ===========================
        float lg0[2][4], lg1[2][4];
        zacc(lg0); zacc(lg1);
        mma_dual<8, 1, 1, 4>(sPk + W2_4, 0, ehA0, ehA1, lg0, lg1, lane);
#pragma unroll
        for (int nt = 0; nt < 2; nt++) {
            int col = nt * 8 + 2 * c;
            float bx = (col < 12)     ? be2[col]     : 0.f;
            float by = (col + 1 < 12) ? be2[col + 1] : 0.f;
            lg0[nt][0] += bx; lg0[nt][1] += by; lg0[nt][2] += bx; lg0[nt][3] += by;
            lg1[nt][0] += bx; lg1[nt][1] += by; lg1[nt][2] += bx; lg1[nt][3] += by;
        }

        // =============== Phase F2: softmax + combine, both tiles ===========
#pragma unroll
        for (int t = 0; t < 2; t++) {
#pragma unroll
            for (int half = 0; half < 2; half++) {
                float v00 = t ? lg1[0][2 * half]     : lg0[0][2 * half];
                float v01 = t ? lg1[0][2 * half + 1] : lg0[0][2 * half + 1];
                float v10 = t ? lg1[1][2 * half]     : lg0[1][2 * half];
                float v11 = t ? lg1[1][2 * half + 1] : lg0[1][2 * half + 1];
                int row = row0 + 16 * t + 8 * half;
                float g0 = gate[t][2 * half + 0];
                float g1 = gate[t][2 * half + 1];

                const float NEG = -1e30f;
                float me0 = (c < 3) ? fmaxf(v00, v01) : NEG;
                float me1 = (c == 3) ? fmaxf(v00, v01)
                                     : ((c < 2) ? fmaxf(v10, v11) : NEG);
                float m0 = qmax(me0), m1 = qmax(me1);

                float mn0 = (c == 3) ? m1 : m0;
                float p00 = __expf(v00 - mn0);
                float p01 = __expf(v01 - mn0);
                float p10 = __expf(v10 - m1);
                float p11 = __expf(v11 - m1);

                float s0l = (c < 3) ? (p00 + p01) : 0.f;
                float s1l = (c == 3) ? (p00 + p01) : ((c < 2) ? (p10 + p11) : 0.f);
                float inv0 = 1.f / qsum(s0l);
                float inv1 = 1.f / qsum(s1l);

                float in0 = (c == 3) ? inv1 : inv0;
                p00 *= in0; p01 *= in0;
                p10 *= inv1; p11 *= inv1;

                size_t eb = (size_t)row * 12;
                __stcs((float2*)&out_expout[eb + 2 * c], make_float2(p00, p01));
                if (c < 2)
                    __stcs((float2*)&out_expout[eb + 8 + 2 * c], make_float2(p10, p11));

                float t0 = g0 * p00, t1 = g0 * p01;
                float u0 = (c == 3) ? g1 * p00 : g1 * p10;
                float u1 = (c == 3) ? g1 * p01 : g1 * p11;
                int src = base + ((c + 3) & 3);
                float w0 = __shfl_sync(0xffffffffu, u0, src);
                float w1 = __shfl_sync(0xffffffffu, u1, src);
                if (c < 3)
                    __stcs((float2*)&out_action[(size_t)row * 6 + 2 * c],
                           make_float2(t0 + w0, t1 + w1));
            }
        }
    }
}

extern "C" void kernel_launch(void* const* d_in, const int* in_sizes, int n_in,
                              void* d_out, int out_size) {
    const float* feat    = (const float*)d_in[0];
    const float* noise   = (const float*)d_in[1];
    const float* Ws0     = (const float*)d_in[2];
    const float* bs0     = (const float*)d_in[3];
    const float* Ws1     = (const float*)d_in[4];
    const float* bs1     = (const float*)d_in[5];
    const float* Wv      = (const float*)d_in[6];
    const float* bv      = (const float*)d_in[7];
    const float* w_gate  = (const float*)d_in[8];
    const float* w_noise = (const float*)d_in[9];
    const float* We1     = (const float*)d_in[10];
    const float* be1     = (const float*)d_in[11];
    const float* We2     = (const float*)d_in[12];
    const float* be2     = (const float*)d_in[13];

    const int B = in_sizes[0] / 128;
    const int nblk = (B + BLK_ROWS - 1) / BLK_ROWS;

    int nsm = 148;
    cudaDeviceGetAttribute(&nsm, cudaDevAttrMultiProcessorCount, 0);
    int grid = (nblk < nsm) ? nblk : nsm;

    float* out        = (float*)d_out;
    float* out_action = out;                       // [B,6]
    float* out_vf     = out + (size_t)B * 6;       // [B,128]
    float* out_expout = out + (size_t)B * 134;     // [B,2,6]

    cudaFuncSetAttribute(mlp_fused_kernel,
                         cudaFuncAttributeMaxDynamicSharedMemorySize, SMEM_BYTES);

    pack_weights<<<22, 256>>>(Ws0, Ws1, Wv, We1, w_gate, w_noise, We2);
    mlp_fused_kernel<<<grid, TPB, SMEM_BYTES>>>(
        feat, noise, bs0, bs1, bv, be1, be2,
        out_action, out_vf, out_expout, nblk, B);
}

// round 16
// speedup vs baseline: 1.0229x; 1.0229x over previous
#include <cuda_runtime.h>
#include <math.h>
#include <cstdint>

// ---------------------------------------------------------------------------
// Round 16: R14 (dual row-tile fp16 m16n8k16, resident 85KB blob, 8 warps,
// barrier-free) + next-block feat L2 prefetch + streaming feat/noise loads +
// MUFU softplus. Output: [action B*6 | vf B*128 | expout B*12] fp32.
// ---------------------------------------------------------------------------

static constexpr int TPB = 256;
static constexpr int BLK_ROWS = 256;   // 8 warps x 32 rows

static constexpr int WS0_4 = 0;
static constexpr int WS1_4 = 2048;
static constexpr int WV_4  = 3072;
static constexpr int WE1_4 = 4096;
static constexpr int W2_4  = 5120;
static constexpr int G_4   = 5376;
static constexpr int PACK_U4 = 5440;
static constexpr int SMEM_BYTES = PACK_U4 * 16;   // 87040

__device__ __align__(16) uint4 g_pack[PACK_U4];

__device__ __forceinline__ unsigned pack_h2(float lo, float hi) {
    unsigned p;
    asm("cvt.rn.f16x2.f32 %0, %1, %2;" : "=r"(p) : "f"(hi), "f"(lo));
    return p;
}
__device__ __forceinline__ float tanh_mufu(float x) {
    float y;
    asm("tanh.approx.f32 %0, %1;" : "=f"(y) : "f"(x));
    return y;
}
__device__ __forceinline__ float softplus_fast(float x) {
    return fmaxf(x, 0.f) + __logf(1.0f + __expf(-fabsf(x)));
}

// ============================ prologue (same as R13/R14) =====================
__global__ void pack_weights(const float* __restrict__ Ws0,
                             const float* __restrict__ Ws1,
                             const float* __restrict__ Wv,
                             const float* __restrict__ We1,
                             const float* __restrict__ wg,
                             const float* __restrict__ wn,
                             const float* __restrict__ We2) {
    int idx = blockIdx.x * blockDim.x + threadIdx.x;
    if (idx >= 5504) return;
    int lane, r, c;

    if (idx < 5376) {
        int base, NTP, panel;
        int i = idx;
        if (i < 2048)      { base = WS0_4; NTP = 8; panel = 0; }
        else if (i < 3072) { base = WS1_4; NTP = 4; panel = 1; i -= 2048; }
        else if (i < 4096) { base = WV_4;  NTP = 8; panel = 2; i -= 3072; }
        else if (i < 5120) { base = WE1_4; NTP = 8; panel = 3; i -= 4096; }
        else               { base = W2_4;  NTP = 1; panel = 4; i -= 5120; }
        lane = i & 31; r = lane >> 2; c = lane & 3;
        int t = i >> 5, ntp = t % NTP, kc = t / NTP;
        int k0 = kc * 16 + 2 * c;

        auto W = [&](int k, int n) -> float {
            switch (panel) {
                case 0: return Ws0[k * 128 + n];
                case 1: return (n < 62) ? Ws1[k * 62 + n] : 0.f;
                case 2: return (k < 62) ? Wv[k * 128 + n] : 0.f;
                case 3: {
                    int e = n >> 6, hid = n & 63;
                    return (k < 62) ? We1[((e * 62 + k) << 6) + hid] : 0.f;
                }
                default: {
                    if (n >= 12) return 0.f;
                    int e = n / 6, o = n - e * 6;
                    return ((k >> 6) == e) ? We2[e * 384 + (k & 63) * 6 + o] : 0.f;
                }
            }
        };
        uint4 q;
        int ne = (2 * ntp) * 8 + r, no = ne + 8;
        q.x = pack_h2(W(k0, ne), W(k0 + 1, ne));
        q.y = pack_h2(W(k0 + 8, ne), W(k0 + 9, ne));
        q.z = pack_h2(W(k0, no), W(k0 + 1, no));
        q.w = pack_h2(W(k0 + 8, no), W(k0 + 9, no));
        g_pack[base + (kc * NTP + ntp) * 32 + lane] = q;
    } else {
        int i = idx - 5376;
        lane = i & 31; r = lane >> 2; c = lane & 3;
        int kc = i >> 5;
        int k0 = kc * 16 + 2 * c, n = r;
        auto G = [&](int k) -> float {
            if (k >= 62) return 0.f;
            if (n < 2) return wg[k * 2 + n];
            if (n < 4) return wn[k * 2 + (n - 2)];
            return 0.f;
        };
        uint2* g2 = (uint2*)(g_pack + G_4);
        g2[kc * 32 + lane] = make_uint2(pack_h2(G(k0), G(k0 + 1)),
                                        pack_h2(G(k0 + 8), G(k0 + 9)));
    }
}

// ============================ MMA helpers ====================================
__device__ __forceinline__ void mma16(float d[4], unsigned a0, unsigned a1,
                                      unsigned a2, unsigned a3,
                                      unsigned b0, unsigned b1) {
    asm("mma.sync.aligned.m16n8k16.row.col.f32.f16.f16.f32 "
        "{%0,%1,%2,%3},{%4,%5,%6,%7},{%8,%9},{%0,%1,%2,%3};"
        : "+f"(d[0]), "+f"(d[1]), "+f"(d[2]), "+f"(d[3])
        : "r"(a0), "r"(a1), "r"(a2), "r"(a3), "r"(b0), "r"(b1));
}

template <int KC, int NTPh, int NTPtot, int UNR>
__device__ __forceinline__ void mma_dual(const uint4* __restrict__ P, int ntp0,
                                         const unsigned (&a0)[KC][4],
                                         const unsigned (&a1)[KC][4],
                                         float (&c0)[2 * NTPh][4],
                                         float (&c1)[2 * NTPh][4], int lane) {
#pragma unroll UNR
    for (int kc = 0; kc < KC; kc++) {
        const uint4* pk = P + (kc * NTPtot + ntp0) * 32 + lane;
#pragma unroll
        for (int ntp = 0; ntp < NTPh; ntp++) {
            uint4 q = pk[ntp * 32];
            mma16(c0[2 * ntp],     a0[kc][0], a0[kc][1], a0[kc][2], a0[kc][3], q.x, q.y);
            mma16(c0[2 * ntp + 1], a0[kc][0], a0[kc][1], a0[kc][2], a0[kc][3], q.z, q.w);
            mma16(c1[2 * ntp],     a1[kc][0], a1[kc][1], a1[kc][2], a1[kc][3], q.x, q.y);
            mma16(c1[2 * ntp + 1], a1[kc][0], a1[kc][1], a1[kc][2], a1[kc][3], q.z, q.w);
        }
    }
}

template <int NT> __device__ __forceinline__ void zacc(float (&acc)[NT][4]) {
#pragma unroll
    for (int i = 0; i < NT; i++)
#pragma unroll
        for (int j = 0; j < 4; j++) acc[i][j] = 0.f;
}

__device__ __forceinline__ float qmax(float v) {
    v = fmaxf(v, __shfl_xor_sync(0xffffffffu, v, 1));
    v = fmaxf(v, __shfl_xor_sync(0xffffffffu, v, 2));
    return v;
}
__device__ __forceinline__ float qsum(float v) {
    v += __shfl_xor_sync(0xffffffffu, v, 1);
    v += __shfl_xor_sync(0xffffffffu, v, 2);
    return v;
}

// ============================ main kernel ====================================
__global__ void __launch_bounds__(TPB, 1) mlp_fused_kernel(
    const float* __restrict__ feat,   const float* __restrict__ noise,
    const float* __restrict__ bs0,    const float* __restrict__ bs1,
    const float* __restrict__ bv,     const float* __restrict__ be1,
    const float* __restrict__ be2,
    float* __restrict__ out_action, float* __restrict__ out_vf,
    float* __restrict__ out_expout, int nblk)
{
    extern __shared__ uint4 sPk[];

    const int tid  = threadIdx.x;
    const int lane = tid & 31;
    const int wrow = (tid >> 5) * 32;
    const int r = lane >> 2, c = lane & 3;
    const int base = lane & ~3;

    for (int i = tid; i < PACK_U4; i += TPB) sPk[i] = g_pack[i];
    __syncthreads();
    const uint2* sG2 = (const uint2*)(sPk + G_4);

    for (int blk = blockIdx.x; blk < nblk; blk += gridDim.x) {
        const int row0 = blk * BLK_ROWS + wrow + r;   // tile0 first row

        // ---- hoist feat A-frags for both tiles (streaming loads) ----
        unsigned aF0[8][4], aF1[8][4];
        {
            const float* f0 = feat + (size_t)row0 * 128;
#pragma unroll
            for (int kc = 0; kc < 8; kc++) {
                int k0 = kc * 16 + 2 * c;
                float2 x0 = __ldcs((const float2*)(f0 + k0));
                float2 x1 = __ldcs((const float2*)(f0 + 8 * 128 + k0));
                float2 x2 = __ldcs((const float2*)(f0 + k0 + 8));
                float2 x3 = __ldcs((const float2*)(f0 + 8 * 128 + k0 + 8));
                aF0[kc][0] = pack_h2(x0.x, x0.y);
                aF0[kc][1] = pack_h2(x1.x, x1.y);
                aF0[kc][2] = pack_h2(x2.x, x2.y);
                aF0[kc][3] = pack_h2(x3.x, x3.y);
                float2 y0 = __ldcs((const float2*)(f0 + 16 * 128 + k0));
                float2 y1 = __ldcs((const float2*)(f0 + 24 * 128 + k0));
                float2 y2 = __ldcs((const float2*)(f0 + 16 * 128 + k0 + 8));
                float2 y3 = __ldcs((const float2*)(f0 + 24 * 128 + k0 + 8));
                aF1[kc][0] = pack_h2(y0.x, y0.y);
                aF1[kc][1] = pack_h2(y1.x, y1.y);
                aF1[kc][2] = pack_h2(y2.x, y2.y);
                aF1[kc][3] = pack_h2(y3.x, y3.y);
            }
        }
        // ---- prefetch next block's feat (this warp's 32 rows) into L2 ----
        {
            int nxt = blk + gridDim.x;
            if (nxt < nblk) {
                const char* pf = (const char*)(feat +
                    (size_t)(nxt * BLK_ROWS + wrow) * 128);
#pragma unroll
                for (int i = 0; i < 4; i++)
                    asm volatile("prefetch.global.L2 [%0];"
                                 :: "l"(pf + (i * 32 + lane) * 128));
            }
        }

        // =============== Phase A: h = tanh(feat @ Ws0 + bs0) — N-split =====
        unsigned aH0[8][4], aH1[8][4];
#pragma unroll
        for (int h = 0; h < 2; h++) {
            float a0[8][4], a1[8][4];
            zacc(a0); zacc(a1);
            mma_dual<8, 4, 8, 4>(sPk + WS0_4, 4 * h, aF0, aF1, a0, a1, lane);
#pragma unroll
            for (int p = 0; p < 4; p++) {
                int kp = 4 * h + p;
                float2 b0 = *(const float2*)&bs0[(2 * kp) * 8 + 2 * c];
                float2 b1 = *(const float2*)&bs0[(2 * kp + 1) * 8 + 2 * c];
                aH0[kp][0] = pack_h2(tanh_mufu(a0[2 * p][0] + b0.x),
                                     tanh_mufu(a0[2 * p][1] + b0.y));
                aH0[kp][1] = pack_h2(tanh_mufu(a0[2 * p][2] + b0.x),
                                     tanh_mufu(a0[2 * p][3] + b0.y));
                aH0[kp][2] = pack_h2(tanh_mufu(a0[2 * p + 1][0] + b1.x),
                                     tanh_mufu(a0[2 * p + 1][1] + b1.y));
                aH0[kp][3] = pack_h2(tanh_mufu(a0[2 * p + 1][2] + b1.x),
                                     tanh_mufu(a0[2 * p + 1][3] + b1.y));
                aH1[kp][0] = pack_h2(tanh_mufu(a1[2 * p][0] + b0.x),
                                     tanh_mufu(a1[2 * p][1] + b0.y));
                aH1[kp][1] = pack_h2(tanh_mufu(a1[2 * p][2] + b0.x),
                                     tanh_mufu(a1[2 * p][3] + b0.y));
                aH1[kp][2] = pack_h2(tanh_mufu(a1[2 * p + 1][0] + b1.x),
                                     tanh_mufu(a1[2 * p + 1][1] + b1.y));
                aH1[kp][3] = pack_h2(tanh_mufu(a1[2 * p + 1][2] + b1.x),
                                     tanh_mufu(a1[2 * p + 1][3] + b1.y));
            }
        }

        // =============== Phase B: la = tanh(h @ Ws1 + bs1), N=64 ===========
        unsigned laA0[4][4], laA1[4][4];
        {
            float a0[8][4], a1[8][4];
            zacc(a0); zacc(a1);
            mma_dual<8, 4, 4, 4>(sPk + WS1_4, 0, aH0, aH1, a0, a1, lane);
#pragma unroll
            for (int kp = 0; kp < 4; kp++) {
                int c0 = (2 * kp) * 8 + 2 * c, c1 = (2 * kp + 1) * 8 + 2 * c;
                float b0x = (c0 < 62) ? bs1[c0] : 0.f;
                float b0y = (c0 + 1 < 62) ? bs1[c0 + 1] : 0.f;
                float b1x = (c1 < 62) ? bs1[c1] : 0.f;
                float b1y = (c1 + 1 < 62) ? bs1[c1 + 1] : 0.f;
                laA0[kp][0] = pack_h2(tanh_mufu(a0[2 * kp][0] + b0x),
                                      tanh_mufu(a0[2 * kp][1] + b0y));
                laA0[kp][1] = pack_h2(tanh_mufu(a0[2 * kp][2] + b0x),
                                      tanh_mufu(a0[2 * kp][3] + b0y));
                laA0[kp][2] = pack_h2(tanh_mufu(a0[2 * kp + 1][0] + b1x),
                                      tanh_mufu(a0[2 * kp + 1][1] + b1y));
                laA0[kp][3] = pack_h2(tanh_mufu(a0[2 * kp + 1][2] + b1x),
                                      tanh_mufu(a0[2 * kp + 1][3] + b1y));
                laA1[kp][0] = pack_h2(tanh_mufu(a1[2 * kp][0] + b0x),
                                      tanh_mufu(a1[2 * kp][1] + b0y));
                laA1[kp][1] = pack_h2(tanh_mufu(a1[2 * kp][2] + b0x),
                                      tanh_mufu(a1[2 * kp][3] + b0y));
                laA1[kp][2] = pack_h2(tanh_mufu(a1[2 * kp + 1][0] + b1x),
                                      tanh_mufu(a1[2 * kp + 1][1] + b1y));
                laA1[kp][3] = pack_h2(tanh_mufu(a1[2 * kp + 1][2] + b1x),
                                      tanh_mufu(a1[2 * kp + 1][3] + b1y));
            }
        }

        // =============== Gating, both tiles (warp-local) ===================
        float gate[2][4];
#pragma unroll
        for (int t = 0; t < 2; t++) {
            float g[4] = {0.f, 0.f, 0.f, 0.f};
#pragma unroll
            for (int kc = 0; kc < 4; kc++) {
                uint2 b = sG2[kc * 32 + lane];
                if (t == 0)
                    mma16(g, laA0[kc][0], laA0[kc][1], laA0[kc][2], laA0[kc][3], b.x, b.y);
                else
                    mma16(g, laA1[kc][0], laA1[kc][1], laA1[kc][2], laA1[kc][3], b.x, b.y);
            }
            float cl0  = __shfl_sync(0xffffffffu, g[0], base);
            float cl1  = __shfl_sync(0xffffffffu, g[1], base);
            float cl0b = __shfl_sync(0xffffffffu, g[2], base);
            float cl1b = __shfl_sync(0xffffffffu, g[3], base);
            float n0p  = __shfl_sync(0xffffffffu, g[0], base + 1);
            float n1p  = __shfl_sync(0xffffffffu, g[1], base + 1);
            float n0pb = __shfl_sync(0xffffffffu, g[2], base + 1);
            float n1pb = __shfl_sync(0xffffffffu, g[3], base + 1);
            int rA = row0 + 16 * t, rB = rA + 8;
            float2 nzA = __ldcs((const float2*)&noise[(size_t)rA * 2]);
            float2 nzB = __ldcs((const float2*)&noise[(size_t)rB * 2]);
            {
                float z0 = fmaf(nzA.x, softplus_fast(n0p) + 1e-2f, cl0);
                float z1 = fmaf(nzA.y, softplus_fast(n1p) + 1e-2f, cl1);
                float mx = fmaxf(z0, z1);
                float e0 = __expf(z0 - mx), e1 = __expf(z1 - mx);
                float inv = 1.f / (e0 + e1);
                gate[t][0] = e0 * inv; gate[t][1] = e1 * inv;
            }
            {
                float z0 = fmaf(nzB.x, softplus_fast(n0pb) + 1e-2f, cl0b);
                float z1 = fmaf(nzB.y, softplus_fast(n1pb) + 1e-2f, cl1b);
                float mx = fmaxf(z0, z1);
                float e0 = __expf(z0 - mx), e1 = __expf(z1 - mx);
                float inv = 1.f / (e0 + e1);
                gate[t][2] = e0 * inv; gate[t][3] = e1 * inv;
            }
        }

        // =============== Phase C: vf = tanh(la @ Wv + bv) — N-split ========
#pragma unroll
        for (int h = 0; h < 2; h++) {
            float a0[8][4], a1[8][4];
            zacc(a0); zacc(a1);
            mma_dual<4, 4, 8, 4>(sPk + WV_4, 4 * h, laA0, laA1, a0, a1, lane);
#pragma unroll
            for (int nt = 0; nt < 8; nt++) {
                int col = 64 * h + nt * 8 + 2 * c;
                float2 bb = *(const float2*)&bv[col];
                float2 o00, o01, o10, o11;
                o00.x = tanh_mufu(a0[nt][0] + bb.x);
                o00.y = tanh_mufu(a0[nt][1] + bb.y);
                o01.x = tanh_mufu(a0[nt][2] + bb.x);
                o01.y = tanh_mufu(a0[nt][3] + bb.y);
                o10.x = tanh_mufu(a1[nt][0] + bb.x);
                o10.y = tanh_mufu(a1[nt][1] + bb.y);
                o11.x = tanh_mufu(a1[nt][2] + bb.x);
                o11.y = tanh_mufu(a1[nt][3] + bb.y);
                __stcs((float2*)&out_vf[(size_t)(row0) * 128 + col],      o00);
                __stcs((float2*)&out_vf[(size_t)(row0 + 8) * 128 + col],  o01);
                __stcs((float2*)&out_vf[(size_t)(row0 + 16) * 128 + col], o10);
                __stcs((float2*)&out_vf[(size_t)(row0 + 24) * 128 + col], o11);
            }
        }

        // =============== Phase E: eh = relu(la @ We1 + be1) — N-split ======
        unsigned ehA0[8][4], ehA1[8][4];
#pragma unroll
        for (int h = 0; h < 2; h++) {
            float a0[8][4], a1[8][4];
            zacc(a0); zacc(a1);
            mma_dual<4, 4, 8, 4>(sPk + WE1_4, 4 * h, laA0, laA1, a0, a1, lane);
#pragma unroll
            for (int p = 0; p < 4; p++) {
                int kp = 4 * h + p;
                float2 b0 = *(const float2*)&be1[(2 * kp) * 8 + 2 * c];
                float2 b1 = *(const float2*)&be1[(2 * kp + 1) * 8 + 2 * c];
                ehA0[kp][0] = pack_h2(fmaxf(a0[2 * p][0] + b0.x, 0.f),
                                      fmaxf(a0[2 * p][1] + b0.y, 0.f));
                ehA0[kp][1] = pack_h2(fmaxf(a0[2 * p][2] + b0.x, 0.f),
                                      fmaxf(a0[2 * p][3] + b0.y, 0.f));
                ehA0[kp][2] = pack_h2(fmaxf(a0[2 * p + 1][0] + b1.x, 0.f),
                                      fmaxf(a0[2 * p + 1][1] + b1.y, 0.f));
                ehA0[kp][3] = pack_h2(fmaxf(a0[2 * p + 1][2] + b1.x, 0.f),
                                      fmaxf(a0[2 * p + 1][3] + b1.y, 0.f));
                ehA1[kp][0] = pack_h2(fmaxf(a1[2 * p][0] + b0.x, 0.f),
                                      fmaxf(a1[2 * p][1] + b0.y, 0.f));
                ehA1[kp][1] = pack_h2(fmaxf(a1[2 * p][2] + b0.x, 0.f),
                                      fmaxf(a1[2 * p][3] + b0.y, 0.f));
                ehA1[kp][2] = pack_h2(fmaxf(a1[2 * p + 1][0] + b1.x, 0.f),
                                      fmaxf(a1[2 * p + 1][1] + b1.y, 0.f));
                ehA1[kp][3] = pack_h2(fmaxf(a1[2 * p + 1][2] + b1.x, 0.f),
                                      fmaxf(a1[2 * p + 1][3] + b1.y, 0.f));
            }
        }

        // =============== Phase F1: logits (N=16) ===========================
        float lg0[2][4], lg1[2][4];
        zacc(lg0); zacc(lg1);
        mma_dual<8, 1, 1, 4>(sPk + W2_4, 0, ehA0, ehA1, lg0, lg1, lane);
#pragma unroll
        for (int nt = 0; nt < 2; nt++) {
            int col = nt * 8 + 2 * c;
            float bx = (col < 12)     ? be2[col]     : 0.f;
            float by = (col + 1 < 12) ? be2[col + 1] : 0.f;
            lg0[nt][0] += bx; lg0[nt][1] += by; lg0[nt][2] += bx; lg0[nt][3] += by;
            lg1[nt][0] += bx; lg1[nt][1] += by; lg1[nt][2] += bx; lg1[nt][3] += by;
        }

        // =============== Phase F2: softmax + combine, both tiles ===========
#pragma unroll
        for (int t = 0; t < 2; t++) {
#pragma unroll
            for (int half = 0; half < 2; half++) {
                float v00 = t ? lg1[0][2 * half]     : lg0[0][2 * half];
                float v01 = t ? lg1[0][2 * half + 1] : lg0[0][2 * half + 1];
                float v10 = t ? lg1[1][2 * half]     : lg0[1][2 * half];
                float v11 = t ? lg1[1][2 * half + 1] : lg0[1][2 * half + 1];
                int row = row0 + 16 * t + 8 * half;
                float g0 = gate[t][2 * half + 0];
                float g1 = gate[t][2 * half + 1];

                const float NEG = -1e30f;
                float me0 = (c < 3) ? fmaxf(v00, v01) : NEG;
                float me1 = (c == 3) ? fmaxf(v00, v01)
                                     : ((c < 2) ? fmaxf(v10, v11) : NEG);
                float m0 = qmax(me0), m1 = qmax(me1);

                float mn0 = (c == 3) ? m1 : m0;
                float p00 = __expf(v00 - mn0);
                float p01 = __expf(v01 - mn0);
                float p10 = __expf(v10 - m1);
                float p11 = __expf(v11 - m1);

                float s0l = (c < 3) ? (p00 + p01) : 0.f;
                float s1l = (c == 3) ? (p00 + p01) : ((c < 2) ? (p10 + p11) : 0.f);
                float inv0 = 1.f / qsum(s0l);
                float inv1 = 1.f / qsum(s1l);

                float in0 = (c == 3) ? inv1 : inv0;
                p00 *= in0; p01 *= in0;
                p10 *= inv1; p11 *= inv1;

                size_t eb = (size_t)row * 12;
                __stcs((float2*)&out_expout[eb + 2 * c], make_float2(p00, p01));
                if (c < 2)
                    __stcs((float2*)&out_expout[eb + 8 + 2 * c], make_float2(p10, p11));

                float t0 = g0 * p00, t1 = g0 * p01;
                float u0 = (c == 3) ? g1 * p00 : g1 * p10;
                float u1 = (c == 3) ? g1 * p01 : g1 * p11;
                int src = base + ((c + 3) & 3);
                float w0 = __shfl_sync(0xffffffffu, u0, src);
                float w1 = __shfl_sync(0xffffffffu, u1, src);
                if (c < 3)
                    __stcs((float2*)&out_action[(size_t)row * 6 + 2 * c],
                           make_float2(t0 + w0, t1 + w1));
            }
        }
    }
}

extern "C" void kernel_launch(void* const* d_in, const int* in_sizes, int n_in,
                              void* d_out, int out_size) {
    const float* feat    = (const float*)d_in[0];
    const float* noise   = (const float*)d_in[1];
    const float* Ws0     = (const float*)d_in[2];
    const float* bs0     = (const float*)d_in[3];
    const float* Ws1     = (const float*)d_in[4];
    const float* bs1     = (const float*)d_in[5];
    const float* Wv      = (const float*)d_in[6];
    const float* bv      = (const float*)d_in[7];
    const float* w_gate  = (const float*)d_in[8];
    const float* w_noise = (const float*)d_in[9];
    const float* We1     = (const float*)d_in[10];
    const float* be1     = (const float*)d_in[11];
    const float* We2     = (const float*)d_in[12];
    const float* be2     = (const float*)d_in[13];

    const int B = in_sizes[0] / 128;
    const int nblk = B / BLK_ROWS;

    int nsm = 148;
    cudaDeviceGetAttribute(&nsm, cudaDevAttrMultiProcessorCount, 0);
    int grid = (nblk < nsm) ? nblk : nsm;

    float* out        = (float*)d_out;
    float* out_action = out;                       // [B,6]
    float* out_vf     = out + (size_t)B * 6;       // [B,128]
    float* out_expout = out + (size_t)B * 134;     // [B,2,6]

    cudaFuncSetAttribute(mlp_fused_kernel,
                         cudaFuncAttributeMaxDynamicSharedMemorySize, SMEM_BYTES);

    pack_weights<<<22, 256>>>(Ws0, Ws1, Wv, We1, w_gate, w_noise, We2);
    mlp_fused_kernel<<<grid, TPB, SMEM_BYTES>>>(
        feat, noise, bs0, bs1, bv, be1, be2,
        out_action, out_vf, out_expout, nblk);
}